// round 1
// baseline (speedup 1.0000x reference)
#include <cuda_runtime.h>

#define BATCH 4096
#define HW 225
#define WIDTH 15
#define DCH 48
#define PCH 16
#define VCH 32
#define PC 2380
#define STR 228

// ---- dynamic smem layout (float offsets) ----
// wdw    @0     432   (conv_w 48x9)
// cb     @432   48
// wpp    @480   256   (ppw 16x16)
// bpp    @736   16
// wpd    @752   144   (pdw 16x9)
// bpd    @896   16
// wpf    @912   16
// wvpT   @928   1024  (vpw transposed: [ci][co])
// bvp    @1952  32
// vsum   @1984  32
// codes  @2016  450 (ints)
// raw    @2468  48*228 = 10944   (reused: pp @2468, pd @2468+3648)
// conv   @13412 48*228 = 10944
// pad    @24356 8     (float4 overread guard)
#define SMEM_FLOATS 24364
#define SMEM_BYTES  (SMEM_FLOATS * 4)

extern "C" __global__ void __launch_bounds__(256, 2)
patnet_kernel(const float* __restrict__ emb,
              const float* __restrict__ conv_w, const float* __restrict__ conv_b,
              const float* __restrict__ ppw_w,  const float* __restrict__ ppw_b,
              const float* __restrict__ pdw_w,  const float* __restrict__ pdw_b,
              const float* __restrict__ pf_w,
              const float* __restrict__ vpw_w,  const float* __restrict__ vpw_b,
              const float* __restrict__ vl1_w,  const float* __restrict__ vl1_b,
              const float* __restrict__ vl2_w,  const float* __restrict__ vl2_b,
              const float* __restrict__ vf_w,   const float* __restrict__ vf_b,
              const int* __restrict__ sparse,   const int* __restrict__ board,
              float* __restrict__ out)
{
    extern __shared__ float sm[];
    float* wdw  = sm;
    float* cb   = sm + 432;
    float* wpp  = sm + 480;
    float* bpp  = sm + 736;
    float* wpd  = sm + 752;
    float* bpd  = sm + 896;
    float* wpf  = sm + 912;
    float* wvpT = sm + 928;
    float* bvp  = sm + 1952;
    float* vsum = sm + 1984;
    int*   codes= (int*)(sm + 2016);
    float* raw  = sm + 2468;
    float* conv = sm + 13412;
    float* pp   = raw;          // aliased after raw is dead
    float* pd   = raw + 3648;

    const int tid = threadIdx.x;
    const int b   = blockIdx.x;

    // ---------- phase 0: load weights into smem, compute codes ----------
    for (int i = tid; i < 432; i += 256) wdw[i] = conv_w[i];
    for (int i = tid; i < 48;  i += 256) cb[i]  = conv_b[i];
    for (int i = tid; i < 256; i += 256) wpp[i] = ppw_w[i];
    for (int i = tid; i < 16;  i += 256) { bpp[i] = ppw_b[i]; bpd[i] = pdw_b[i]; wpf[i] = pf_w[i]; }
    for (int i = tid; i < 144; i += 256) wpd[i] = pdw_w[i];
    for (int i = tid; i < 1024; i += 256) {
        int co = i >> 5, ci = i & 31;
        wvpT[ci * 32 + co] = vpw_w[i];
    }
    for (int i = tid; i < 32; i += 256) { bvp[i] = vpw_b[i]; vsum[i] = 0.0f; }

    for (int i = tid; i < 450; i += 256) {
        int j = i / 225, p = i - j * 225;
        int sp = sparse[b * 2700 + (10 + j) * 225 + p];
        int bd = board[b * 450 + j * 225 + p];
        int c = (bd > 0) ? PC : sp;
        codes[i] = c + j * (PC + 1);
    }
    __syncthreads();

    // ---------- phase 1: embedding gather + sum -> raw[c][p] ----------
    for (int i = tid; i < DCH * HW; i += 256) {
        int p = i / DCH, c = i - p * DCH;
        int c0 = codes[p], c1 = codes[225 + p];
        raw[c * STR + p] = emb[c0 * DCH + c] + emb[c1 * DCH + c];
    }
    __syncthreads();

    // ---------- phase 2: depthwise 3x3 conv (48 ch) + relu -> conv ----------
    for (int i = tid; i < DCH * HW; i += 256) {
        int c = i / HW, pos = i - c * HW;
        int h = pos / WIDTH, w = pos - h * WIDTH;
        float acc = cb[c];
        const float* src = raw + c * STR;
        const float* wk  = wdw + c * 9;
        #pragma unroll
        for (int ky = 0; ky < 3; ky++) {
            int hh = h + ky - 1;
            if ((unsigned)hh < WIDTH) {
                #pragma unroll
                for (int kx = 0; kx < 3; kx++) {
                    int ww = w + kx - 1;
                    if ((unsigned)ww < WIDTH)
                        acc += src[hh * WIDTH + ww] * wk[ky * 3 + kx];
                }
            }
        }
        conv[c * STR + pos] = fmaxf(acc, 0.0f);
    }
    __syncthreads();

    // ---------- phase 3a: value 1x1 conv 32->32 + relu + spatial sum ----------
    // register tile: 29 pos-groups x 8 co-groups = 232 threads, 8 pos x 4 co each
    if (tid < 232) {
        const int pg  = tid >> 3;
        const int cg  = tid & 7;
        const int co0 = cg * 4;
        const int p0  = pg * 8;
        float acc[8][4];
        #pragma unroll
        for (int j = 0; j < 8; j++) {
            acc[j][0] = bvp[co0];     acc[j][1] = bvp[co0 + 1];
            acc[j][2] = bvp[co0 + 2]; acc[j][3] = bvp[co0 + 3];
        }
        #pragma unroll 4
        for (int ci = 0; ci < 32; ci++) {
            const float4 w4 = *(const float4*)&wvpT[ci * 32 + co0];
            const float* src = &conv[(PCH + ci) * STR + p0];
            const float4 a0 = *(const float4*)src;
            const float4 a1 = *(const float4*)(src + 4);
            const float in8[8] = {a0.x, a0.y, a0.z, a0.w, a1.x, a1.y, a1.z, a1.w};
            #pragma unroll
            for (int j = 0; j < 8; j++) {
                acc[j][0] += in8[j] * w4.x;
                acc[j][1] += in8[j] * w4.y;
                acc[j][2] += in8[j] * w4.z;
                acc[j][3] += in8[j] * w4.w;
            }
        }
        #pragma unroll
        for (int k = 0; k < 4; k++) {
            float s = 0.0f;
            #pragma unroll
            for (int j = 0; j < 8; j++)
                if (p0 + j < HW) s += fmaxf(acc[j][k], 0.0f);
            atomicAdd(&vsum[co0 + k], s);
        }
    }

    // ---------- phase 3b: policy 1x1 conv 16->16 + relu -> pp ----------
    for (int i = tid; i < PCH * HW; i += 256) {
        int co = i / HW, pos = i - co * HW;
        float acc = bpp[co];
        const float* wk = wpp + co * 16;
        #pragma unroll
        for (int ci = 0; ci < 16; ci++)
            acc += wk[ci] * conv[ci * STR + pos];
        pp[co * STR + pos] = fmaxf(acc, 0.0f);
    }
    __syncthreads();

    // ---------- phase 4: policy depthwise 3x3 (16 ch) + relu -> pd ----------
    for (int i = tid; i < PCH * HW; i += 256) {
        int c = i / HW, pos = i - c * HW;
        int h = pos / WIDTH, w = pos - h * WIDTH;
        float acc = bpd[c];
        const float* src = pp + c * STR;
        const float* wk  = wpd + c * 9;
        #pragma unroll
        for (int ky = 0; ky < 3; ky++) {
            int hh = h + ky - 1;
            if ((unsigned)hh < WIDTH) {
                #pragma unroll
                for (int kx = 0; kx < 3; kx++) {
                    int ww = w + kx - 1;
                    if ((unsigned)ww < WIDTH)
                        acc += src[hh * WIDTH + ww] * wk[ky * 3 + kx];
                }
            }
        }
        pd[c * STR + pos] = fmaxf(acc, 0.0f);
    }
    __syncthreads();

    // ---------- phase 5: pf 16->1 (threads 0..223) | value FC head (warp 7) ----------
    if (tid < 224) {
        for (int pos = tid; pos < HW; pos += 224) {
            float acc = 0.0f;
            #pragma unroll
            for (int ci = 0; ci < 16; ci++)
                acc += wpf[ci] * pd[ci * STR + pos];
            out[BATCH * 3 + b * HW + pos] = acc;
        }
    } else {
        const int lane = tid - 224;
        float v = vsum[lane] * (1.0f / 225.0f);
        float h1 = vl1_b[lane];
        #pragma unroll
        for (int i = 0; i < 32; i++)
            h1 += vl1_w[lane * 32 + i] * __shfl_sync(0xffffffffu, v, i);
        h1 = fmaxf(h1, 0.0f);
        float h2 = vl2_b[lane];
        #pragma unroll
        for (int i = 0; i < 32; i++)
            h2 += vl2_w[lane * 32 + i] * __shfl_sync(0xffffffffu, h1, i);
        h2 = fmaxf(h2, 0.0f);
        float o = (lane < 3) ? vf_b[lane] : 0.0f;
        #pragma unroll
        for (int i = 0; i < 32; i++) {
            float t = __shfl_sync(0xffffffffu, h2, i);
            if (lane < 3) o += vf_w[lane * 32 + i] * t;
        }
        if (lane < 3) out[b * 3 + lane] = o;
    }
}

extern "C" void kernel_launch(void* const* d_in, const int* in_sizes, int n_in,
                              void* d_out, int out_size) {
    (void)in_sizes; (void)n_in; (void)out_size;
    cudaFuncSetAttribute(patnet_kernel,
                         cudaFuncAttributeMaxDynamicSharedMemorySize, SMEM_BYTES);
    patnet_kernel<<<BATCH, 256, SMEM_BYTES>>>(
        (const float*)d_in[0],  (const float*)d_in[1],  (const float*)d_in[2],
        (const float*)d_in[3],  (const float*)d_in[4],  (const float*)d_in[5],
        (const float*)d_in[6],  (const float*)d_in[7],  (const float*)d_in[8],
        (const float*)d_in[9],  (const float*)d_in[10], (const float*)d_in[11],
        (const float*)d_in[12], (const float*)d_in[13], (const float*)d_in[14],
        (const float*)d_in[15], (const int*)d_in[16],   (const int*)d_in[17],
        (float*)d_out);
}

// round 2
// speedup vs baseline: 1.6053x; 1.6053x over previous
#include <cuda_runtime.h>

#define BATCH 4096
#define HW 225
#define WIDTH 15
#define DCH 48
#define PCH 16
#define VCH 32
#define PC 2380
#define STR 228
#define CHUNK 16

// ---- smem layout (float offsets) ----
#define OFF_WDW   0        // 432  conv_w 48x9
#define OFF_CB    432      // 48
#define OFF_WPD   480      // 144  pdw 16x9
#define OFF_BPD   624      // 16
#define OFF_WPF   640      // 16
#define OFF_BPP   656      // 16
#define OFF_BVP   672      // 32
#define OFF_VSUM  704      // 32
#define OFF_CODES 736      // 450 ints
#define OFF_WPP2  1188     // 512  ppw transposed dup-pairs [ci][co] float2
#define OFF_WVP2  1700     // 2048 vpw transposed dup-pairs [ci][co] float2
#define OFF_RAW   3748     // 16*228+4 = 3652 (aliased: pp)
#define OFF_CONV  7400     // 48*228+8 = 10952 (ch 0..15 aliased: pd)
#define SMEM_FLOATS 18352
#define SMEM_BYTES  (SMEM_FLOATS * 4)

typedef unsigned long long ull;

__device__ __forceinline__ void ffma2(ull& d, ull a, ull b) {
    asm("fma.rn.f32x2 %0, %1, %2, %0;" : "+l"(d) : "l"(a), "l"(b));
}
__device__ __forceinline__ ull pk2(float x, float y) {
    ull r; asm("mov.b64 %0, {%1, %2};" : "=l"(r) : "f"(x), "f"(y)); return r;
}
__device__ __forceinline__ float2 unpk(ull v) {
    float2 f; asm("mov.b64 {%0, %1}, %2;" : "=f"(f.x), "=f"(f.y) : "l"(v)); return f;
}

extern "C" __global__ void __launch_bounds__(256, 3)
patnet_kernel(const float* __restrict__ emb,
              const float* __restrict__ conv_w, const float* __restrict__ conv_b,
              const float* __restrict__ ppw_w,  const float* __restrict__ ppw_b,
              const float* __restrict__ pdw_w,  const float* __restrict__ pdw_b,
              const float* __restrict__ pf_w,
              const float* __restrict__ vpw_w,  const float* __restrict__ vpw_b,
              const float* __restrict__ vl1_w,  const float* __restrict__ vl1_b,
              const float* __restrict__ vl2_w,  const float* __restrict__ vl2_b,
              const float* __restrict__ vf_w,   const float* __restrict__ vf_b,
              const int* __restrict__ sparse,   const int* __restrict__ board,
              float* __restrict__ out)
{
    extern __shared__ float sm[];
    float* wdw  = sm + OFF_WDW;
    float* cb   = sm + OFF_CB;
    float* wpd  = sm + OFF_WPD;
    float* bpd  = sm + OFF_BPD;
    float* wpf  = sm + OFF_WPF;
    float* bpp  = sm + OFF_BPP;
    float* bvp  = sm + OFF_BVP;
    float* vsum = sm + OFF_VSUM;
    int*   codes= (int*)(sm + OFF_CODES);
    float* wpp2 = sm + OFF_WPP2;
    float* wvp2 = sm + OFF_WVP2;
    float* raw  = sm + OFF_RAW;      // also pp
    float* conv = sm + OFF_CONV;     // ch 0..15 later reused as pd
    float* pp   = raw;
    float* pd   = conv;

    const int tid = threadIdx.x;
    const int b   = blockIdx.x;

    // ---------- phase 0: weights -> smem, codes ----------
    for (int i = tid; i < 432; i += 256) wdw[i] = conv_w[i];
    for (int i = tid; i < 48;  i += 256) cb[i]  = conv_b[i];
    for (int i = tid; i < 144; i += 256) wpd[i] = pdw_w[i];
    if (tid < 16) { bpd[tid] = pdw_b[tid]; wpf[tid] = pf_w[tid]; bpp[tid] = ppw_b[tid]; }
    if (tid >= 32 && tid < 64) { bvp[tid-32] = vpw_b[tid-32]; vsum[tid-32] = 0.0f; }
    for (int i = tid; i < 256; i += 256) {
        int co = i >> 4, ci = i & 15;
        float w = ppw_w[i];
        ((float2*)wpp2)[ci * 16 + co] = make_float2(w, w);
    }
    for (int i = tid; i < 1024; i += 256) {
        int co = i >> 5, ci = i & 31;
        float w = vpw_w[i];
        ((float2*)wvp2)[ci * 32 + co] = make_float2(w, w);
    }
    for (int i = tid; i < 450; i += 256) {
        int j = i / 225, p = i - j * 225;
        int sp = sparse[b * 2700 + (10 + j) * 225 + p];
        int bd = board[b * 450 + j * 225 + p];
        int c = (bd > 0) ? PC : sp;
        codes[i] = c + j * (PC + 1);
    }

    // ---------- phases 1..3: per 16-ch chunk: gather -> depthwise 3x3 ----------
    #pragma unroll 1
    for (int chunk = 0; chunk < 3; chunk++) {
        const int cb16 = chunk * CHUNK;
        __syncthreads();
        if (tid < HW) {
            const int c0 = codes[tid], c1 = codes[225 + tid];
            const float4* e0 = (const float4*)(emb + c0 * DCH + cb16);
            const float4* e1 = (const float4*)(emb + c1 * DCH + cb16);
            float4 x0 = e0[0], x1 = e0[1], x2 = e0[2], x3 = e0[3];
            float4 y0 = e1[0], y1 = e1[1], y2 = e1[2], y3 = e1[3];
            float* dst = raw + tid;
            dst[0*STR]  = x0.x + y0.x;  dst[1*STR]  = x0.y + y0.y;
            dst[2*STR]  = x0.z + y0.z;  dst[3*STR]  = x0.w + y0.w;
            dst[4*STR]  = x1.x + y1.x;  dst[5*STR]  = x1.y + y1.y;
            dst[6*STR]  = x1.z + y1.z;  dst[7*STR]  = x1.w + y1.w;
            dst[8*STR]  = x2.x + y2.x;  dst[9*STR]  = x2.y + y2.y;
            dst[10*STR] = x2.z + y2.z;  dst[11*STR] = x2.w + y2.w;
            dst[12*STR] = x3.x + y3.x;  dst[13*STR] = x3.y + y3.y;
            dst[14*STR] = x3.z + y3.z;  dst[15*STR] = x3.w + y3.w;
        }
        __syncthreads();
        if (tid < 240) {
            const int w    = tid % 15;
            const int cloc = tid / 15;
            const int c    = cb16 + cloc;
            const float* wk = wdw + c * 9;
            const float k0=wk[0],k1=wk[1],k2=wk[2],k3=wk[3],k4=wk[4],k5=wk[5],k6=wk[6],k7=wk[7],k8=wk[8];
            const float bias = cb[c];
            const bool wl = (w > 0), wr = (w < 14);
            const float* src = raw + cloc * STR + w;
            float* dst = conv + c * STR + w;
            float a0=0.f,a1=0.f,a2=0.f;
            float b0 = wl ? src[-1] : 0.f;
            float b1 = src[0];
            float b2 = wr ? src[1] : 0.f;
            #pragma unroll
            for (int h = 0; h < 15; h++) {
                float c0v, c1v, c2v;
                if (h < 14) {
                    const float* r = src + (h + 1) * 15;
                    c0v = wl ? r[-1] : 0.f;
                    c1v = r[0];
                    c2v = wr ? r[1] : 0.f;
                } else { c0v = c1v = c2v = 0.f; }
                float acc = bias
                    + a0*k0 + a1*k1 + a2*k2
                    + b0*k3 + b1*k4 + b2*k5
                    + c0v*k6 + c1v*k7 + c2v*k8;
                dst[h * 15] = fmaxf(acc, 0.0f);
                a0=b0; a1=b1; a2=b2; b0=c0v; b1=c1v; b2=c2v;
            }
        }
    }
    __syncthreads();

    // ---------- phase 4: val 1x1 32->32 (f32x2) then pol 1x1 16->16 (f32x2) ----------
    if (tid < 232) {
        const int pg = tid >> 3, cg = tid & 7;
        const int p0 = pg * 8;
        {   // value pointwise: 4 co per thread
            const int co0 = cg * 4;
            ull acc[4][4];
            #pragma unroll
            for (int k = 0; k < 4; k++) {
                ull bi = pk2(bvp[co0 + k], bvp[co0 + k]);
                acc[0][k] = bi; acc[1][k] = bi; acc[2][k] = bi; acc[3][k] = bi;
            }
            #pragma unroll 8
            for (int ci = 0; ci < 32; ci++) {
                const ulonglong2* ip = (const ulonglong2*)&conv[(PCH + ci) * STR + p0];
                ulonglong2 iA = ip[0], iB = ip[1];
                const ulonglong2* wp = (const ulonglong2*)&wvp2[(ci * 32 + co0) * 2];
                ulonglong2 wA = wp[0], wB = wp[1];
                ffma2(acc[0][0], iA.x, wA.x); ffma2(acc[1][0], iA.y, wA.x);
                ffma2(acc[2][0], iB.x, wA.x); ffma2(acc[3][0], iB.y, wA.x);
                ffma2(acc[0][1], iA.x, wA.y); ffma2(acc[1][1], iA.y, wA.y);
                ffma2(acc[2][1], iB.x, wA.y); ffma2(acc[3][1], iB.y, wA.y);
                ffma2(acc[0][2], iA.x, wB.x); ffma2(acc[1][2], iA.y, wB.x);
                ffma2(acc[2][2], iB.x, wB.x); ffma2(acc[3][2], iB.y, wB.x);
                ffma2(acc[0][3], iA.x, wB.y); ffma2(acc[1][3], iA.y, wB.y);
                ffma2(acc[2][3], iB.x, wB.y); ffma2(acc[3][3], iB.y, wB.y);
            }
            #pragma unroll
            for (int k = 0; k < 4; k++) {
                float s = 0.0f;
                #pragma unroll
                for (int jj = 0; jj < 4; jj++) {
                    float2 f = unpk(acc[jj][k]);
                    int p = p0 + 2 * jj;
                    if (p < HW)     s += fmaxf(f.x, 0.0f);
                    if (p + 1 < HW) s += fmaxf(f.y, 0.0f);
                }
                atomicAdd(&vsum[co0 + k], s);
            }
        }
        {   // policy pointwise: 2 co per thread
            const int co0 = cg * 2;
            ull acc[4][2];
            #pragma unroll
            for (int k = 0; k < 2; k++) {
                ull bi = pk2(bpp[co0 + k], bpp[co0 + k]);
                acc[0][k] = bi; acc[1][k] = bi; acc[2][k] = bi; acc[3][k] = bi;
            }
            #pragma unroll 8
            for (int ci = 0; ci < 16; ci++) {
                const ulonglong2* ip = (const ulonglong2*)&conv[ci * STR + p0];
                ulonglong2 iA = ip[0], iB = ip[1];
                const ulonglong2* wp = (const ulonglong2*)&wpp2[(ci * 16 + co0) * 2];
                ulonglong2 wA = wp[0];
                ffma2(acc[0][0], iA.x, wA.x); ffma2(acc[1][0], iA.y, wA.x);
                ffma2(acc[2][0], iB.x, wA.x); ffma2(acc[3][0], iB.y, wA.x);
                ffma2(acc[0][1], iA.x, wA.y); ffma2(acc[1][1], iA.y, wA.y);
                ffma2(acc[2][1], iB.x, wA.y); ffma2(acc[3][1], iB.y, wA.y);
            }
            #pragma unroll
            for (int k = 0; k < 2; k++) {
                float* dstc = pp + (co0 + k) * STR;
                #pragma unroll
                for (int jj = 0; jj < 4; jj++) {
                    float2 f = unpk(acc[jj][k]);
                    int p = p0 + 2 * jj;
                    if (p < HW)     dstc[p]     = fmaxf(f.x, 0.0f);
                    if (p + 1 < HW) dstc[p + 1] = fmaxf(f.y, 0.0f);
                }
            }
        }
    }
    __syncthreads();

    // ---------- phase 5: policy depthwise 3x3 (16 ch) -> pd (= conv[0:16]) ----------
    if (tid < 240) {
        const int w = tid % 15;
        const int c = tid / 15;
        const float* wk = wpd + c * 9;
        const float k0=wk[0],k1=wk[1],k2=wk[2],k3=wk[3],k4=wk[4],k5=wk[5],k6=wk[6],k7=wk[7],k8=wk[8];
        const float bias = bpd[c];
        const bool wl = (w > 0), wr = (w < 14);
        const float* src = pp + c * STR + w;
        float* dst = pd + c * STR + w;
        float a0=0.f,a1=0.f,a2=0.f;
        float b0 = wl ? src[-1] : 0.f;
        float b1 = src[0];
        float b2 = wr ? src[1] : 0.f;
        #pragma unroll
        for (int h = 0; h < 15; h++) {
            float c0v, c1v, c2v;
            if (h < 14) {
                const float* r = src + (h + 1) * 15;
                c0v = wl ? r[-1] : 0.f;
                c1v = r[0];
                c2v = wr ? r[1] : 0.f;
            } else { c0v = c1v = c2v = 0.f; }
            float acc = bias
                + a0*k0 + a1*k1 + a2*k2
                + b0*k3 + b1*k4 + b2*k5
                + c0v*k6 + c1v*k7 + c2v*k8;
            dst[h * 15] = fmaxf(acc, 0.0f);
            a0=b0; a1=b1; a2=b2; b0=c0v; b1=c1v; b2=c2v;
        }
    }
    __syncthreads();

    // ---------- phase 6: pf 16->1 (threads 0..223) | value FC head (warp 7) ----------
    if (tid < 224) {
        for (int pos = tid; pos < HW; pos += 224) {
            float acc = 0.0f;
            #pragma unroll
            for (int ci = 0; ci < 16; ci++)
                acc += wpf[ci] * pd[ci * STR + pos];
            out[BATCH * 3 + b * HW + pos] = acc;
        }
    }
    if (tid >= 224) {
        const int lane = tid - 224;
        float v = vsum[lane] * (1.0f / 225.0f);
        float h1 = vl1_b[lane];
        #pragma unroll
        for (int i = 0; i < 32; i++)
            h1 += vl1_w[lane * 32 + i] * __shfl_sync(0xffffffffu, v, i);
        h1 = fmaxf(h1, 0.0f);
        float h2 = vl2_b[lane];
        #pragma unroll
        for (int i = 0; i < 32; i++)
            h2 += vl2_w[lane * 32 + i] * __shfl_sync(0xffffffffu, h1, i);
        h2 = fmaxf(h2, 0.0f);
        float o = (lane < 3) ? vf_b[lane] : 0.0f;
        #pragma unroll
        for (int i = 0; i < 32; i++) {
            float t = __shfl_sync(0xffffffffu, h2, i);
            if (lane < 3) o += vf_w[lane * 32 + i] * t;
        }
        if (lane < 3) out[b * 3 + lane] = o;
    }
}

extern "C" void kernel_launch(void* const* d_in, const int* in_sizes, int n_in,
                              void* d_out, int out_size) {
    (void)in_sizes; (void)n_in; (void)out_size;
    cudaFuncSetAttribute(patnet_kernel,
                         cudaFuncAttributeMaxDynamicSharedMemorySize, SMEM_BYTES);
    patnet_kernel<<<BATCH, 256, SMEM_BYTES>>>(
        (const float*)d_in[0],  (const float*)d_in[1],  (const float*)d_in[2],
        (const float*)d_in[3],  (const float*)d_in[4],  (const float*)d_in[5],
        (const float*)d_in[6],  (const float*)d_in[7],  (const float*)d_in[8],
        (const float*)d_in[9],  (const float*)d_in[10], (const float*)d_in[11],
        (const float*)d_in[12], (const float*)d_in[13], (const float*)d_in[14],
        (const float*)d_in[15], (const int*)d_in[16],   (const int*)d_in[17],
        (float*)d_out);
}

// round 3
// speedup vs baseline: 2.0434x; 1.2729x over previous
#include <cuda_runtime.h>

#define BATCH 4096
#define PC 2380
#define RW 16            // slots per board row (15 cols + 1 ghost)
#define NSLOT 240        // 15*16
#define STR2 244         // channel stride (floats), mult of 4

// ---- smem layout (float offsets) ----
#define OFF_WDW   0      // 432  conv_w 48x9
#define OFF_CB    432    // 48
#define OFF_WPD   480    // 144  pdw 16x9
#define OFF_BPD   624    // 16
#define OFF_WPF   640    // 16
#define OFF_BPP   656    // 16
#define OFF_BVP   672    // 32
#define OFF_VSUM  704    // 32
#define OFF_CODES 736    // 450 ints -> 1186
#define OFF_WPPT  1188   // 256   ppw transposed [ci][co]
#define OFF_WVPT  1444   // 1024  vpw transposed [ci][co] -> 2468
#define OFF_RAW   2468   // 16*244 = 3904 -> 6372   (aliased: pp)
#define OFF_CONV  6372   // 48*244 = 11712 -> 18084 (rows 0..15 aliased: pd)
#define SMEM_FLOATS 18100
#define SMEM_BYTES  (SMEM_FLOATS * 4)

typedef unsigned long long ull;

__device__ __forceinline__ void ffma2(ull& d, ull a, ull b) {
    asm("fma.rn.f32x2 %0, %1, %2, %0;" : "+l"(d) : "l"(a), "l"(b));
}
__device__ __forceinline__ ull pk2(float x, float y) {
    ull r; asm("mov.b64 %0, {%1, %2};" : "=l"(r) : "f"(x), "f"(y)); return r;
}
__device__ __forceinline__ float2 unpk(ull v) {
    float2 f; asm("mov.b64 {%0, %1}, %2;" : "=f"(f.x), "=f"(f.y) : "l"(v)); return f;
}

// depthwise 3x3 over one channel, 4-column strip, sliding 3-row register window
__device__ __forceinline__ void dwconv4(const float* __restrict__ src,
                                        float* __restrict__ dst,
                                        const float* __restrict__ wk,
                                        float bias, int wg)
{
    const int w0 = wg * 4;
    const bool hasL = (wg > 0), notlast = (wg < 3);
    const float k0=wk[0],k1=wk[1],k2=wk[2],k3=wk[3],k4=wk[4],k5=wk[5],k6=wk[6],k7=wk[7],k8=wk[8];
    float al=0.f,a0=0.f,a1=0.f,a2=0.f,a3=0.f,ar=0.f;
    float bl,b0,b1,b2,b3,br;
    {
        float4 m = *(const float4*)(src + w0);
        bl = hasL ? src[w0 - 1] : 0.f;
        br = notlast ? src[w0 + 4] : 0.f;
        b0 = m.x; b1 = m.y; b2 = m.z; b3 = m.w;
    }
    #pragma unroll
    for (int h = 0; h < 15; h++) {
        float cl, c0, c1, c2, c3, cr;
        if (h < 14) {
            const float* r = src + (h + 1) * RW;
            float4 m = *(const float4*)(r + w0);
            cl = hasL ? r[w0 - 1] : 0.f;
            cr = notlast ? r[w0 + 4] : 0.f;
            c0 = m.x; c1 = m.y; c2 = m.z; c3 = m.w;
        } else { cl = c0 = c1 = c2 = c3 = cr = 0.f; }
        float o0 = bias + al*k0+a0*k1+a1*k2 + bl*k3+b0*k4+b1*k5 + cl*k6+c0*k7+c1*k8;
        float o1 = bias + a0*k0+a1*k1+a2*k2 + b0*k3+b1*k4+b2*k5 + c0*k6+c1*k7+c2*k8;
        float o2 = bias + a1*k0+a2*k1+a3*k2 + b1*k3+b2*k4+b3*k5 + c1*k6+c2*k7+c3*k8;
        float o3 = bias + a2*k0+a3*k1+ar*k2 + b2*k3+b3*k4+br*k5 + c2*k6+c3*k7+cr*k8;
        *(float4*)(dst + h * RW + w0) =
            make_float4(fmaxf(o0,0.f), fmaxf(o1,0.f), fmaxf(o2,0.f), fmaxf(o3,0.f));
        al=bl; a0=b0; a1=b1; a2=b2; a3=b3; ar=br;
        bl=cl; b0=c0; b1=c1; b2=c2; b3=c3; br=cr;
    }
}

extern "C" __global__ void __launch_bounds__(256, 3)
patnet_kernel(const float* __restrict__ emb,
              const float* __restrict__ conv_w, const float* __restrict__ conv_b,
              const float* __restrict__ ppw_w,  const float* __restrict__ ppw_b,
              const float* __restrict__ pdw_w,  const float* __restrict__ pdw_b,
              const float* __restrict__ pf_w,
              const float* __restrict__ vpw_w,  const float* __restrict__ vpw_b,
              const float* __restrict__ vl1_w,  const float* __restrict__ vl1_b,
              const float* __restrict__ vl2_w,  const float* __restrict__ vl2_b,
              const float* __restrict__ vf_w,   const float* __restrict__ vf_b,
              const int* __restrict__ sparse,   const int* __restrict__ board,
              float* __restrict__ out)
{
    extern __shared__ float sm[];
    float* wdw  = sm + OFF_WDW;
    float* cb   = sm + OFF_CB;
    float* wpd  = sm + OFF_WPD;
    float* bpd  = sm + OFF_BPD;
    float* wpf  = sm + OFF_WPF;
    float* bpp  = sm + OFF_BPP;
    float* bvp  = sm + OFF_BVP;
    float* vsum = sm + OFF_VSUM;
    int*   codes= (int*)(sm + OFF_CODES);
    float* wppT = sm + OFF_WPPT;
    float* wvpT = sm + OFF_WVPT;
    float* raw  = sm + OFF_RAW;      // also pp
    float* conv = sm + OFF_CONV;     // rows 0..15 later reused as pd
    float* pp   = raw;
    float* pd   = conv;

    const int tid = threadIdx.x;
    const int b   = blockIdx.x;

    // ---------- phase 0: weights -> smem, codes, ghost-column zeroing ----------
    for (int i = tid; i < 432; i += 256) wdw[i] = conv_w[i];
    for (int i = tid; i < 48;  i += 256) cb[i]  = conv_b[i];
    for (int i = tid; i < 144; i += 256) wpd[i] = pdw_w[i];
    if (tid < 16) { bpd[tid] = pdw_b[tid]; wpf[tid] = pf_w[tid]; bpp[tid] = ppw_b[tid]; }
    if (tid >= 32 && tid < 64) { bvp[tid-32] = vpw_b[tid-32]; vsum[tid-32] = 0.0f; }
    for (int i = tid; i < 256; i += 256) {
        int co = i >> 4, ci = i & 15;
        wppT[ci * 16 + co] = ppw_w[i];
    }
    for (int i = tid; i < 1024; i += 256) {
        int co = i >> 5, ci = i & 31;
        wvpT[ci * 32 + co] = vpw_w[i];
    }
    if (tid < 240) {        // zero ghost column (w=15) of raw, all 16 rows x 15 h
        int c = tid / 15, h = tid - c * 15;
        raw[c * STR2 + h * RW + 15] = 0.0f;
    }
    for (int i = tid; i < 450; i += 256) {
        int j = i / 225, p = i - j * 225;
        int sp = sparse[b * 2700 + (10 + j) * 225 + p];
        int bd = board[b * 450 + j * 225 + p];
        int c = (bd > 0) ? PC : sp;
        codes[i] = c + j * (PC + 1);
    }

    // ---------- phases 1..2 per 16-channel chunk: gather -> depthwise 3x3 ----------
    #pragma unroll 1
    for (int chunk = 0; chunk < 3; chunk++) {
        const int cb16 = chunk * 16;
        __syncthreads();
        if (tid < 225) {
            const int h = tid / 15, w = tid - h * 15;
            const int slot = h * RW + w;
            const int c0 = codes[tid], c1 = codes[225 + tid];
            const float4* e0 = (const float4*)(emb + c0 * 48 + cb16);
            const float4* e1 = (const float4*)(emb + c1 * 48 + cb16);
            float4 x0 = e0[0], x1 = e0[1], x2 = e0[2], x3 = e0[3];
            float4 y0 = e1[0], y1 = e1[1], y2 = e1[2], y3 = e1[3];
            float* dst = raw + slot;
            dst[0*STR2]  = x0.x + y0.x;  dst[1*STR2]  = x0.y + y0.y;
            dst[2*STR2]  = x0.z + y0.z;  dst[3*STR2]  = x0.w + y0.w;
            dst[4*STR2]  = x1.x + y1.x;  dst[5*STR2]  = x1.y + y1.y;
            dst[6*STR2]  = x1.z + y1.z;  dst[7*STR2]  = x1.w + y1.w;
            dst[8*STR2]  = x2.x + y2.x;  dst[9*STR2]  = x2.y + y2.y;
            dst[10*STR2] = x2.z + y2.z;  dst[11*STR2] = x2.w + y2.w;
            dst[12*STR2] = x3.x + y3.x;  dst[13*STR2] = x3.y + y3.y;
            dst[14*STR2] = x3.z + y3.z;  dst[15*STR2] = x3.w + y3.w;
        }
        __syncthreads();
        if (tid < 64) {
            const int cloc = tid >> 2, wg = tid & 3;
            const int c = cb16 + cloc;
            dwconv4(raw + cloc * STR2, conv + c * STR2, wdw + c * 9, cb[c], wg);
        }
    }
    __syncthreads();

    // ---------- phase 4a: value 1x1 32->32 (f32x2, 4 slots x 8 co), all 256 threads ----
    {
        const int pg = tid >> 2, cg = tid & 3;
        const bool live = (pg < 60);
        const int p0 = live ? pg * 4 : 0;
        const int co0 = cg * 8;
        ull acc[2][8];
        #pragma unroll
        for (int k = 0; k < 8; k++) {
            float bv = bvp[co0 + k];
            ull bi = pk2(bv, bv);
            acc[0][k] = bi; acc[1][k] = bi;
        }
        #pragma unroll 8
        for (int ci = 0; ci < 32; ci++) {
            ulonglong2 iv = *(const ulonglong2*)&conv[(16 + ci) * STR2 + p0];
            float4 wA = *(const float4*)&wvpT[ci * 32 + co0];
            float4 wB = *(const float4*)&wvpT[ci * 32 + co0 + 4];
            ull w0 = pk2(wA.x, wA.x), w1 = pk2(wA.y, wA.y);
            ull w2 = pk2(wA.z, wA.z), w3 = pk2(wA.w, wA.w);
            ull w4 = pk2(wB.x, wB.x), w5 = pk2(wB.y, wB.y);
            ull w6 = pk2(wB.z, wB.z), w7 = pk2(wB.w, wB.w);
            ffma2(acc[0][0], iv.x, w0); ffma2(acc[1][0], iv.y, w0);
            ffma2(acc[0][1], iv.x, w1); ffma2(acc[1][1], iv.y, w1);
            ffma2(acc[0][2], iv.x, w2); ffma2(acc[1][2], iv.y, w2);
            ffma2(acc[0][3], iv.x, w3); ffma2(acc[1][3], iv.y, w3);
            ffma2(acc[0][4], iv.x, w4); ffma2(acc[1][4], iv.y, w4);
            ffma2(acc[0][5], iv.x, w5); ffma2(acc[1][5], iv.y, w5);
            ffma2(acc[0][6], iv.x, w6); ffma2(acc[1][6], iv.y, w6);
            ffma2(acc[0][7], iv.x, w7); ffma2(acc[1][7], iv.y, w7);
        }
        const int lane = tid & 31;
        #pragma unroll
        for (int k = 0; k < 8; k++) {
            float s = 0.0f;
            #pragma unroll
            for (int j = 0; j < 2; j++) {
                float2 f = unpk(acc[j][k]);
                int s0 = p0 + 2 * j;
                bool v0 = live && ((s0 & 15) < 15);
                bool v1 = live && (((s0 + 1) & 15) < 15);
                if (v0) s += fmaxf(f.x, 0.0f);
                if (v1) s += fmaxf(f.y, 0.0f);
            }
            s += __shfl_xor_sync(0xffffffffu, s, 4);
            s += __shfl_xor_sync(0xffffffffu, s, 8);
            s += __shfl_xor_sync(0xffffffffu, s, 16);
            if (lane < 4) atomicAdd(&vsum[co0 + k], s);
        }
    }

    // ---------- phase 4b: policy 1x1 16->16 (f32x2, 4 slots x 8 co), 120 threads ----
    if (tid < 120) {
        const int pg = tid >> 1, cg = tid & 1;
        const int p0 = pg * 4;
        const int co0 = cg * 8;
        ull acc[2][8];
        #pragma unroll
        for (int k = 0; k < 8; k++) {
            float bv = bpp[co0 + k];
            ull bi = pk2(bv, bv);
            acc[0][k] = bi; acc[1][k] = bi;
        }
        #pragma unroll
        for (int ci = 0; ci < 16; ci++) {
            ulonglong2 iv = *(const ulonglong2*)&conv[ci * STR2 + p0];
            float4 wA = *(const float4*)&wppT[ci * 16 + co0];
            float4 wB = *(const float4*)&wppT[ci * 16 + co0 + 4];
            ull w0 = pk2(wA.x, wA.x), w1 = pk2(wA.y, wA.y);
            ull w2 = pk2(wA.z, wA.z), w3 = pk2(wA.w, wA.w);
            ull w4 = pk2(wB.x, wB.x), w5 = pk2(wB.y, wB.y);
            ull w6 = pk2(wB.z, wB.z), w7 = pk2(wB.w, wB.w);
            ffma2(acc[0][0], iv.x, w0); ffma2(acc[1][0], iv.y, w0);
            ffma2(acc[0][1], iv.x, w1); ffma2(acc[1][1], iv.y, w1);
            ffma2(acc[0][2], iv.x, w2); ffma2(acc[1][2], iv.y, w2);
            ffma2(acc[0][3], iv.x, w3); ffma2(acc[1][3], iv.y, w3);
            ffma2(acc[0][4], iv.x, w4); ffma2(acc[1][4], iv.y, w4);
            ffma2(acc[0][5], iv.x, w5); ffma2(acc[1][5], iv.y, w5);
            ffma2(acc[0][6], iv.x, w6); ffma2(acc[1][6], iv.y, w6);
            ffma2(acc[0][7], iv.x, w7); ffma2(acc[1][7], iv.y, w7);
        }
        #pragma unroll
        for (int k = 0; k < 8; k++) {
            float* dstc = pp + (co0 + k) * STR2;
            #pragma unroll
            for (int j = 0; j < 2; j++) {
                int s0 = p0 + 2 * j;
                float2 f = unpk(acc[j][k]);
                f.x = fmaxf(f.x, 0.0f);
                f.y = ((s0 & 15) == 14) ? 0.0f : fmaxf(f.y, 0.0f);  // zero ghost col
                *(float2*)(dstc + s0) = f;
            }
        }
    }
    __syncthreads();

    // ---------- phase 5: policy depthwise 3x3 (16 ch) -> pd ----------
    if (tid < 64) {
        const int c = tid >> 2, wg = tid & 3;
        dwconv4(pp + c * STR2, pd + c * STR2, wpd + c * 9, bpd[c], wg);
    }
    __syncthreads();

    // ---------- phase 6: pf 16->1 (tid<120, 2 slots each) | value FC (warp 7) ----
    if (tid < 120) {
        #pragma unroll
        for (int j = 0; j < 2; j++) {
            int s = 2 * tid + j;
            int w = s & 15, h = s >> 4;
            if (w < 15) {
                float acc = 0.0f;
                #pragma unroll
                for (int ci = 0; ci < 16; ci++)
                    acc += wpf[ci] * pd[ci * STR2 + s];
                out[BATCH * 3 + b * 225 + h * 15 + w] = acc;
            }
        }
    }
    if (tid >= 224) {
        const int lane = tid - 224;
        float v = vsum[lane] * (1.0f / 225.0f);
        float h1 = vl1_b[lane];
        #pragma unroll
        for (int i = 0; i < 32; i++)
            h1 += vl1_w[lane * 32 + i] * __shfl_sync(0xffffffffu, v, i);
        h1 = fmaxf(h1, 0.0f);
        float h2 = vl2_b[lane];
        #pragma unroll
        for (int i = 0; i < 32; i++)
            h2 += vl2_w[lane * 32 + i] * __shfl_sync(0xffffffffu, h1, i);
        h2 = fmaxf(h2, 0.0f);
        float o = (lane < 3) ? vf_b[lane] : 0.0f;
        #pragma unroll
        for (int i = 0; i < 32; i++) {
            float t = __shfl_sync(0xffffffffu, h2, i);
            if (lane < 3) o += vf_w[lane * 32 + i] * t;
        }
        if (lane < 3) out[b * 3 + lane] = o;
    }
}

extern "C" void kernel_launch(void* const* d_in, const int* in_sizes, int n_in,
                              void* d_out, int out_size) {
    (void)in_sizes; (void)n_in; (void)out_size;
    cudaFuncSetAttribute(patnet_kernel,
                         cudaFuncAttributeMaxDynamicSharedMemorySize, SMEM_BYTES);
    patnet_kernel<<<BATCH, 256, SMEM_BYTES>>>(
        (const float*)d_in[0],  (const float*)d_in[1],  (const float*)d_in[2],
        (const float*)d_in[3],  (const float*)d_in[4],  (const float*)d_in[5],
        (const float*)d_in[6],  (const float*)d_in[7],  (const float*)d_in[8],
        (const float*)d_in[9],  (const float*)d_in[10], (const float*)d_in[11],
        (const float*)d_in[12], (const float*)d_in[13], (const float*)d_in[14],
        (const float*)d_in[15], (const int*)d_in[16],   (const int*)d_in[17],
        (float*)d_out);
}

// round 4
// speedup vs baseline: 2.2366x; 1.0946x over previous
#include <cuda_runtime.h>

#define BATCH 4096
#define PC 2380
#define RW 16            // padded row width (15 cols + ghost)
#define STR2 244         // channel stride in floats (mult of 4)

// ---- smem layout (float offsets) ----
#define OFF_WDW   0      // 432  conv_w 48x9
#define OFF_CB    432    // 48
#define OFF_WPD   480    // 144  pdw 16x9
#define OFF_BPD   624    // 16
#define OFF_WPF   640    // 16
#define OFF_BPP   656    // 16
#define OFF_BVP   672    // 32
#define OFF_VSUM  704    // 32
#define OFF_CODES 736    // 450 ints -> 1186
#define OFF_WPPT  1188   // 256   ppw transposed [ci][co]
#define OFF_WVPT  1444   // 1024  vpw transposed [ci][co]
#define OFF_RAW   2468   // 48*244 = 11712  (aliased: pp on rows 0..15)
#define OFF_CONV  14180  // 48*244 = 11712  (rows 0..15 aliased: pd)
#define SMEM_FLOATS 25900
#define SMEM_BYTES  (SMEM_FLOATS * 4)

typedef unsigned long long ull;

__device__ __forceinline__ void ffma2(ull& d, ull a, ull b) {
    asm("fma.rn.f32x2 %0, %1, %2, %0;" : "+l"(d) : "l"(a), "l"(b));
}
__device__ __forceinline__ ull pk2(float x, float y) {
    ull r; asm("mov.b64 %0, {%1, %2};" : "=l"(r) : "f"(x), "f"(y)); return r;
}
__device__ __forceinline__ float2 unpk(ull v) {
    float2 f; asm("mov.b64 {%0, %1}, %2;" : "=f"(f.x), "=f"(f.y) : "l"(v)); return f;
}

// depthwise 3x3, one channel, 4-col strip, output rows [H0,H1), sliding window
template<int H0, int H1>
__device__ __forceinline__ void dwconv4(const float* __restrict__ src,
                                        float* __restrict__ dst,
                                        const float* __restrict__ wk,
                                        float bias, int wg)
{
    const int w0 = wg * 4;
    const bool hasL = (wg > 0), hasR = (wg < 3);
    const float k0=wk[0],k1=wk[1],k2=wk[2],k3=wk[3],k4=wk[4],k5=wk[5],k6=wk[6],k7=wk[7],k8=wk[8];
    float al,a0,a1,a2,a3,ar, bl,b0,b1,b2,b3,br;
    if (H0 > 0) {
        const float* r = src + (H0 - 1) * RW;
        float4 m = *(const float4*)(r + w0);
        al = hasL ? r[w0 - 1] : 0.f;  ar = hasR ? r[w0 + 4] : 0.f;
        a0 = m.x; a1 = m.y; a2 = m.z; a3 = m.w;
    } else { al=a0=a1=a2=a3=ar=0.f; }
    {
        const float* r = src + H0 * RW;
        float4 m = *(const float4*)(r + w0);
        bl = hasL ? r[w0 - 1] : 0.f;  br = hasR ? r[w0 + 4] : 0.f;
        b0 = m.x; b1 = m.y; b2 = m.z; b3 = m.w;
    }
    #pragma unroll
    for (int h = H0; h < H1; h++) {
        float cl, c0, c1, c2, c3, cr;
        if (h + 1 < 15) {
            const float* r = src + (h + 1) * RW;
            float4 m = *(const float4*)(r + w0);
            cl = hasL ? r[w0 - 1] : 0.f;  cr = hasR ? r[w0 + 4] : 0.f;
            c0 = m.x; c1 = m.y; c2 = m.z; c3 = m.w;
        } else { cl = c0 = c1 = c2 = c3 = cr = 0.f; }
        float o0 = bias + al*k0+a0*k1+a1*k2 + bl*k3+b0*k4+b1*k5 + cl*k6+c0*k7+c1*k8;
        float o1 = bias + a0*k0+a1*k1+a2*k2 + b0*k3+b1*k4+b2*k5 + c0*k6+c1*k7+c2*k8;
        float o2 = bias + a1*k0+a2*k1+a3*k2 + b1*k3+b2*k4+b3*k5 + c1*k6+c2*k7+c3*k8;
        float o3 = bias + a2*k0+a3*k1+ar*k2 + b2*k3+b3*k4+br*k5 + c2*k6+c3*k7+cr*k8;
        *(float4*)(dst + h * RW + w0) =
            make_float4(fmaxf(o0,0.f), fmaxf(o1,0.f), fmaxf(o2,0.f), fmaxf(o3,0.f));
        al=bl; a0=b0; a1=b1; a2=b2; a3=b3; ar=br;
        bl=cl; b0=c0; b1=c1; b2=c2; b3=c3; br=cr;
    }
}

extern "C" __global__ void __launch_bounds__(256, 2)
patnet_kernel(const float* __restrict__ emb,
              const float* __restrict__ conv_w, const float* __restrict__ conv_b,
              const float* __restrict__ ppw_w,  const float* __restrict__ ppw_b,
              const float* __restrict__ pdw_w,  const float* __restrict__ pdw_b,
              const float* __restrict__ pf_w,
              const float* __restrict__ vpw_w,  const float* __restrict__ vpw_b,
              const float* __restrict__ vl1_w,  const float* __restrict__ vl1_b,
              const float* __restrict__ vl2_w,  const float* __restrict__ vl2_b,
              const float* __restrict__ vf_w,   const float* __restrict__ vf_b,
              const int* __restrict__ sparse,   const int* __restrict__ board,
              float* __restrict__ out)
{
    extern __shared__ float sm[];
    float* wdw  = sm + OFF_WDW;
    float* cb   = sm + OFF_CB;
    float* wpd  = sm + OFF_WPD;
    float* bpd  = sm + OFF_BPD;
    float* wpf  = sm + OFF_WPF;
    float* bpp  = sm + OFF_BPP;
    float* bvp  = sm + OFF_BVP;
    float* vsum = sm + OFF_VSUM;
    int*   codes= (int*)(sm + OFF_CODES);
    float* wppT = sm + OFF_WPPT;
    float* wvpT = sm + OFF_WVPT;
    float* raw  = sm + OFF_RAW;
    float* conv = sm + OFF_CONV;
    float* pp   = raw;            // rows 0..15, after raw dead
    float* pd   = conv;           // rows 0..15, after pol-pw reads done

    const int tid = threadIdx.x;
    const int b   = blockIdx.x;

    // ---------- P0: weights -> smem, codes ----------
    for (int i = tid; i < 432; i += 256) wdw[i] = conv_w[i];
    for (int i = tid; i < 48;  i += 256) cb[i]  = conv_b[i];
    for (int i = tid; i < 144; i += 256) wpd[i] = pdw_w[i];
    if (tid < 16) { bpd[tid] = pdw_b[tid]; wpf[tid] = pf_w[tid]; bpp[tid] = ppw_b[tid]; }
    if (tid >= 32 && tid < 64) { bvp[tid-32] = vpw_b[tid-32]; vsum[tid-32] = 0.0f; }
    for (int i = tid; i < 256; i += 256) {
        int co = i >> 4, ci = i & 15;
        wppT[ci * 16 + co] = ppw_w[i];
    }
    for (int i = tid; i < 1024; i += 256) {
        int co = i >> 5, ci = i & 31;
        wvpT[ci * 32 + co] = vpw_w[i];
    }
    for (int i = tid; i < 450; i += 256) {
        int j = i / 225, p = i - j * 225;
        int sp = sparse[b * 2700 + (10 + j) * 225 + p];
        int bd = board[b * 450 + j * 225 + p];
        int c = (bd > 0) ? PC : sp;
        codes[i] = c + j * (PC + 1);
    }
    __syncthreads();

    // ---------- P1: gather all 48 ch, register transpose, vector STS ----------
    if (tid < 240) {
        #pragma unroll
        for (int task = 0; task < 3; task++) {
            const int t = tid + task * 240;
            const int cblk = t / 60, g = t - cblk * 60;
            const int h = g >> 2, w0 = (g & 3) * 4;
            const int cb4 = cblk * 4;
            float4 v[4];
            #pragma unroll
            for (int j = 0; j < 4; j++) {
                int w = w0 + j;
                if (w < 15) {
                    int p = h * 15 + w;
                    int c0 = codes[p], c1 = codes[225 + p];
                    float4 a = *(const float4*)(emb + c0 * 48 + cb4);
                    float4 bb = *(const float4*)(emb + c1 * 48 + cb4);
                    v[j] = make_float4(a.x+bb.x, a.y+bb.y, a.z+bb.z, a.w+bb.w);
                } else v[j] = make_float4(0.f, 0.f, 0.f, 0.f);
            }
            float* base = raw + h * RW + w0;
            *(float4*)(base + (cb4+0)*STR2) = make_float4(v[0].x, v[1].x, v[2].x, v[3].x);
            *(float4*)(base + (cb4+1)*STR2) = make_float4(v[0].y, v[1].y, v[2].y, v[3].y);
            *(float4*)(base + (cb4+2)*STR2) = make_float4(v[0].z, v[1].z, v[2].z, v[3].z);
            *(float4*)(base + (cb4+3)*STR2) = make_float4(v[0].w, v[1].w, v[2].w, v[3].w);
        }
    }
    __syncthreads();

    // ---------- P2: main depthwise 3x3, 48 ch, 192 threads ----------
    if (tid < 192) {
        const int c = tid >> 2, wg = tid & 3;
        dwconv4<0, 15>(raw + c * STR2, conv + c * STR2, wdw + c * 9, cb[c], wg);
    }
    __syncthreads();

    // ---------- P3a: value 1x1 32->32, f32x2, S=8 C=4, all 256 threads ----------
    {
        const int cg = tid & 7, pgi = tid >> 3;
        const bool live = (pgi < 30);
        const int p0 = live ? pgi * 8 : 0;
        const int co0 = cg * 4;
        ull acc[4][4];
        {
            float4 bv = *(const float4*)&bvp[co0];
            ull b0 = pk2(bv.x, bv.x), b1 = pk2(bv.y, bv.y);
            ull b2 = pk2(bv.z, bv.z), b3 = pk2(bv.w, bv.w);
            #pragma unroll
            for (int j = 0; j < 4; j++) {
                acc[j][0] = b0; acc[j][1] = b1; acc[j][2] = b2; acc[j][3] = b3;
            }
        }
        #pragma unroll 8
        for (int ci = 0; ci < 32; ci++) {
            const ulonglong2* ip = (const ulonglong2*)&conv[(16 + ci) * STR2 + p0];
            ulonglong2 iA = ip[0], iB = ip[1];
            float4 w4 = *(const float4*)&wvpT[ci * 32 + co0];
            ull w0 = pk2(w4.x, w4.x), w1 = pk2(w4.y, w4.y);
            ull w2 = pk2(w4.z, w4.z), w3 = pk2(w4.w, w4.w);
            ffma2(acc[0][0], iA.x, w0); ffma2(acc[1][0], iA.y, w0);
            ffma2(acc[2][0], iB.x, w0); ffma2(acc[3][0], iB.y, w0);
            ffma2(acc[0][1], iA.x, w1); ffma2(acc[1][1], iA.y, w1);
            ffma2(acc[2][1], iB.x, w1); ffma2(acc[3][1], iB.y, w1);
            ffma2(acc[0][2], iA.x, w2); ffma2(acc[1][2], iA.y, w2);
            ffma2(acc[2][2], iB.x, w2); ffma2(acc[3][2], iB.y, w2);
            ffma2(acc[0][3], iA.x, w3); ffma2(acc[1][3], iA.y, w3);
            ffma2(acc[2][3], iB.x, w3); ffma2(acc[3][3], iB.y, w3);
        }
        const int lane = tid & 31;
        #pragma unroll
        for (int k = 0; k < 4; k++) {
            float s = 0.0f;
            #pragma unroll
            for (int j = 0; j < 4; j++) {
                float2 f = unpk(acc[j][k]);
                int s0 = p0 + 2 * j;
                if (live && ((s0 & 15) != 15))       s += fmaxf(f.x, 0.0f);
                if (live && (((s0 + 1) & 15) != 15)) s += fmaxf(f.y, 0.0f);
            }
            s += __shfl_xor_sync(0xffffffffu, s, 8);
            s += __shfl_xor_sync(0xffffffffu, s, 16);
            if (lane < 8) atomicAdd(&vsum[lane * 4 + k], s);
        }
    }

    // ---------- P3b: policy 1x1 16->16, f32x2, S=8 C=4, tid<120 ----------
    if (tid < 120) {
        const int pgi = tid >> 2, cg = tid & 3;
        const int p0 = pgi * 8, co0 = cg * 4;
        ull acc[4][4];
        {
            float4 bv = *(const float4*)&bpp[co0];
            ull b0 = pk2(bv.x, bv.x), b1 = pk2(bv.y, bv.y);
            ull b2 = pk2(bv.z, bv.z), b3 = pk2(bv.w, bv.w);
            #pragma unroll
            for (int j = 0; j < 4; j++) {
                acc[j][0] = b0; acc[j][1] = b1; acc[j][2] = b2; acc[j][3] = b3;
            }
        }
        #pragma unroll
        for (int ci = 0; ci < 16; ci++) {
            const ulonglong2* ip = (const ulonglong2*)&conv[ci * STR2 + p0];
            ulonglong2 iA = ip[0], iB = ip[1];
            float4 w4 = *(const float4*)&wppT[ci * 16 + co0];
            ull w0 = pk2(w4.x, w4.x), w1 = pk2(w4.y, w4.y);
            ull w2 = pk2(w4.z, w4.z), w3 = pk2(w4.w, w4.w);
            ffma2(acc[0][0], iA.x, w0); ffma2(acc[1][0], iA.y, w0);
            ffma2(acc[2][0], iB.x, w0); ffma2(acc[3][0], iB.y, w0);
            ffma2(acc[0][1], iA.x, w1); ffma2(acc[1][1], iA.y, w1);
            ffma2(acc[2][1], iB.x, w1); ffma2(acc[3][1], iB.y, w1);
            ffma2(acc[0][2], iA.x, w2); ffma2(acc[1][2], iA.y, w2);
            ffma2(acc[2][2], iB.x, w2); ffma2(acc[3][2], iB.y, w2);
            ffma2(acc[0][3], iA.x, w3); ffma2(acc[1][3], iA.y, w3);
            ffma2(acc[2][3], iB.x, w3); ffma2(acc[3][3], iB.y, w3);
        }
        const bool ghost = ((p0 & 15) == 8);   // slot p0+7 is ghost
        #pragma unroll
        for (int k = 0; k < 4; k++) {
            float2 f0 = unpk(acc[0][k]), f1 = unpk(acc[1][k]);
            float2 f2 = unpk(acc[2][k]), f3 = unpk(acc[3][k]);
            float4 oA = make_float4(fmaxf(f0.x,0.f), fmaxf(f0.y,0.f),
                                    fmaxf(f1.x,0.f), fmaxf(f1.y,0.f));
            float4 oB = make_float4(fmaxf(f2.x,0.f), fmaxf(f2.y,0.f),
                                    fmaxf(f3.x,0.f), ghost ? 0.f : fmaxf(f3.y,0.f));
            float* dstc = pp + (co0 + k) * STR2 + p0;
            *(float4*)(dstc)     = oA;
            *(float4*)(dstc + 4) = oB;
        }
    }
    __syncthreads();

    // ---------- P4: policy depthwise (tid<128, row-split) | value FC (warp 7) ----------
    if (tid < 128) {
        const int c = tid >> 3, sub = tid & 7;
        const int wg = sub & 3, half = sub >> 2;
        if (half == 0)
            dwconv4<0, 8>(pp + c * STR2, pd + c * STR2, wpd + c * 9, bpd[c], wg);
        else
            dwconv4<8, 15>(pp + c * STR2, pd + c * STR2, wpd + c * 9, bpd[c], wg);
    }
    if (tid >= 224) {
        const int lane = tid - 224;
        float v = vsum[lane] * (1.0f / 225.0f);
        float h1 = vl1_b[lane];
        #pragma unroll
        for (int i = 0; i < 32; i++)
            h1 += vl1_w[lane * 32 + i] * __shfl_sync(0xffffffffu, v, i);
        h1 = fmaxf(h1, 0.0f);
        float h2 = vl2_b[lane];
        #pragma unroll
        for (int i = 0; i < 32; i++)
            h2 += vl2_w[lane * 32 + i] * __shfl_sync(0xffffffffu, h1, i);
        h2 = fmaxf(h2, 0.0f);
        float o = (lane < 3) ? vf_b[lane] : 0.0f;
        #pragma unroll
        for (int i = 0; i < 32; i++) {
            float t = __shfl_sync(0xffffffffu, h2, i);
            if (lane < 3) o += vf_w[lane * 32 + i] * t;
        }
        if (lane < 3) out[b * 3 + lane] = o;
    }
    __syncthreads();

    // ---------- P5: pf 16->1, f32x2, tid<120 (2 slots each) ----------
    if (tid < 120) {
        const int s0 = 2 * tid;
        ull acc = 0;
        #pragma unroll
        for (int ci = 0; ci < 16; ci++) {
            ull iv = *(const ull*)&pd[ci * STR2 + s0];
            ffma2(acc, iv, pk2(wpf[ci], wpf[ci]));
        }
        float2 f = unpk(acc);
        const int w = s0 & 15, h = s0 >> 4;
        float* ob = out + BATCH * 3 + b * 225 + h * 15 + w;
        ob[0] = f.x;
        if (w < 14) ob[1] = f.y;
    }
}

extern "C" void kernel_launch(void* const* d_in, const int* in_sizes, int n_in,
                              void* d_out, int out_size) {
    (void)in_sizes; (void)n_in; (void)out_size;
    cudaFuncSetAttribute(patnet_kernel,
                         cudaFuncAttributeMaxDynamicSharedMemorySize, SMEM_BYTES);
    patnet_kernel<<<BATCH, 256, SMEM_BYTES>>>(
        (const float*)d_in[0],  (const float*)d_in[1],  (const float*)d_in[2],
        (const float*)d_in[3],  (const float*)d_in[4],  (const float*)d_in[5],
        (const float*)d_in[6],  (const float*)d_in[7],  (const float*)d_in[8],
        (const float*)d_in[9],  (const float*)d_in[10], (const float*)d_in[11],
        (const float*)d_in[12], (const float*)d_in[13], (const float*)d_in[14],
        (const float*)d_in[15], (const int*)d_in[16],   (const int*)d_in[17],
        (float*)d_out);
}